// round 6
// baseline (speedup 1.0000x reference)
#include <cuda_runtime.h>
#include <cuda_bf16.h>
#include <math.h>
#include <stdint.h>

#define B   2
#define T   2048
#define C   2048
#define H   16
#define KV  4
#define D   128
#define LP  64
#define GROUPS (H / KV)
#define LSEQ (T - LP)            // 1984
#define SCALE 0.08838834764831845f   // 1/sqrt(128)

// ---------------- scratch (static device globals: allowed) ----------------
__device__ float g_q[(size_t)B * H * T * D];          // [B,H,T,D]
__device__ float g_k[(size_t)B * KV * T * D];         // [B,KV,T,D]
__device__ float g_v[(size_t)B * KV * T * D];         // [B,KV,T,D]
__device__ float g_s[(size_t)B * H * T * T];          // [B,H,T,T] 537 MB
__device__ float g_o[(size_t)B * T * H * D];          // [B,T,H*D]

// ---------------------------------------------------------------------------
// tf32 helpers
// ---------------------------------------------------------------------------
__device__ __forceinline__ uint32_t f2tf(float x) {
    uint32_t r;
    asm("cvt.rna.tf32.f32 %0, %1;" : "=r"(r) : "f"(x));
    return r;
}

// split fp32 -> (tf32 hi, tf32 lo), packed as float2 bit-patterns
__device__ __forceinline__ float2 split_tf32(float x) {
    uint32_t hi = f2tf(x);
    uint32_t lo = f2tf(x - __uint_as_float(hi));
    float2 p;
    p.x = __uint_as_float(hi);
    p.y = __uint_as_float(lo);
    return p;
}

__device__ __forceinline__ void mma_tf32(float c[4],
                                         const uint32_t a[4],
                                         const uint32_t b[2]) {
    asm volatile(
        "mma.sync.aligned.m16n8k8.row.col.f32.tf32.tf32.f32 "
        "{%0,%1,%2,%3},{%4,%5,%6,%7},{%8,%9},{%0,%1,%2,%3};"
        : "+f"(c[0]), "+f"(c[1]), "+f"(c[2]), "+f"(c[3])
        : "r"(a[0]), "r"(a[1]), "r"(a[2]), "r"(a[3]), "r"(b[0]), "r"(b[1]));
}

// ---------------------------------------------------------------------------
// Core: 128x128 output tile, K-step 16, 256 threads (8 warps, 2x4 layout,
// 64x32 warp tiles). 3xTF32 with hi/lo split done ONCE at smem-store time.
// smem tiles hold float2(hi,lo), row pitch 131 (262 words mod 32 = 6 ->
// conflict-free for both transposed stores and fragment loads).
// ---------------------------------------------------------------------------
#define SPITCH 131

template<bool TRANSB>
__device__ __forceinline__ void gemm_core(const float* __restrict__ A,
                                          const float* __restrict__ Bm,
                                          int Kdim, int lda, int ldb,
                                          int m0, int n0,
                                          float acc[4][4][4])
{
    __shared__ float2 As[16][SPITCH];   // [k][m] hi/lo
    __shared__ float2 Bs[16][SPITCH];   // [k][n] hi/lo

    const int tid  = threadIdx.x;
    const int lane = tid & 31;
    const int warp = tid >> 5;
    const int gid  = lane >> 2;        // 0..7
    const int tig  = lane & 3;         // 0..3
    const int wm   = (warp >> 2) * 64; // warp M offset (0/64)
    const int wn   = (warp & 3) * 32;  // warp N offset (0/32/64/96)

    const int ar  = tid >> 2;          // 0..63 (A / B^T tile row)
    const int ac4 = (tid & 3) * 4;     // k offset, float4
    const int br  = tid >> 4;          // 0..15 (row-major B k row)
    const int bc  = (tid & 15) * 4;    // n offset, float4

    for (int k0 = 0; k0 < Kdim; k0 += 16) {
        // ---- A tile: load fp32, split, store transposed [k][m] ----
#pragma unroll
        for (int half = 0; half < 2; half++) {
            int row = ar + half * 64;
            float4 v = *reinterpret_cast<const float4*>(
                &A[(size_t)(m0 + row) * lda + k0 + ac4]);
            As[ac4 + 0][row] = split_tf32(v.x);
            As[ac4 + 1][row] = split_tf32(v.y);
            As[ac4 + 2][row] = split_tf32(v.z);
            As[ac4 + 3][row] = split_tf32(v.w);
        }
        // ---- B tile into [k][n] ----
        if (TRANSB) {
#pragma unroll
            for (int half = 0; half < 2; half++) {
                int row = ar + half * 64;
                float4 v = *reinterpret_cast<const float4*>(
                    &Bm[(size_t)(n0 + row) * ldb + k0 + ac4]);
                Bs[ac4 + 0][row] = split_tf32(v.x);
                Bs[ac4 + 1][row] = split_tf32(v.y);
                Bs[ac4 + 2][row] = split_tf32(v.z);
                Bs[ac4 + 3][row] = split_tf32(v.w);
            }
        } else {
#pragma unroll
            for (int half = 0; half < 2; half++) {
                float4 v = *reinterpret_cast<const float4*>(
                    &Bm[(size_t)(k0 + br) * ldb + n0 + bc + half * 64]);
                int col = bc + half * 64;
                Bs[br][col + 0] = split_tf32(v.x);
                Bs[br][col + 1] = split_tf32(v.y);
                Bs[br][col + 2] = split_tf32(v.z);
                Bs[br][col + 3] = split_tf32(v.w);
            }
        }
        __syncthreads();

#pragma unroll
        for (int ks = 0; ks < 2; ks++) {
            uint32_t ahi[4][4], alo[4][4];
#pragma unroll
            for (int mf = 0; mf < 4; mf++)
#pragma unroll
                for (int r = 0; r < 4; r++) {
                    int krow = ks * 8 + tig + (r >> 1) * 4;
                    int mcol = wm + mf * 16 + gid + (r & 1) * 8;
                    float2 p = As[krow][mcol];
                    ahi[mf][r] = __float_as_uint(p.x);
                    alo[mf][r] = __float_as_uint(p.y);
                }
            uint32_t bhi[4][2], blo[4][2];
#pragma unroll
            for (int nf = 0; nf < 4; nf++)
#pragma unroll
                for (int r = 0; r < 2; r++) {
                    int krow = ks * 8 + tig + r * 4;
                    int ncol = wn + nf * 8 + gid;
                    float2 p = Bs[krow][ncol];
                    bhi[nf][r] = __float_as_uint(p.x);
                    blo[nf][r] = __float_as_uint(p.y);
                }
#pragma unroll
            for (int mf = 0; mf < 4; mf++)
#pragma unroll
                for (int nf = 0; nf < 4; nf++) {
                    mma_tf32(acc[mf][nf], ahi[mf], bhi[nf]);
                    mma_tf32(acc[mf][nf], ahi[mf], blo[nf]);
                    mma_tf32(acc[mf][nf], alo[mf], bhi[nf]);
                }
        }
        __syncthreads();
    }
}

// Epilogue coordinate helper (per fragment register). Variadic so the body
// may contain commas.
#define EPI_LOOP(ROW_EXPR, COL_EXPR, ...)                                    \
    {                                                                        \
        const int lane = threadIdx.x & 31;                                   \
        const int warp = threadIdx.x >> 5;                                   \
        const int gid = lane >> 2, tig = lane & 3;                           \
        const int wm = (warp >> 2) * 64, wn = (warp & 3) * 32;               \
        _Pragma("unroll") for (int mf = 0; mf < 4; mf++)                     \
        _Pragma("unroll") for (int nf = 0; nf < 4; nf++)                     \
        _Pragma("unroll") for (int r = 0; r < 4; r++) {                      \
            int row = (ROW_EXPR) + wm + mf * 16 + gid + ((r >> 1) * 8);      \
            int col = (COL_EXPR) + wn + nf * 8 + tig * 2 + (r & 1);          \
            float val = acc[mf][nf][r];                                      \
            __VA_ARGS__                                                      \
        }                                                                    \
    }

// ---------------------------------------------------------------------------
// Projections: out = hs @ W + bias, optional scatter to [B,NH,T,D]
// ---------------------------------------------------------------------------
__global__ void __launch_bounds__(256)
proj_mma(const float* __restrict__ A, const float* __restrict__ W,
         const float* __restrict__ bias, float* __restrict__ out,
         int N, int Kdim, int NH)
{
    const int m0 = blockIdx.y * 128, n0 = blockIdx.x * 128;
    float acc[4][4][4] = {};
    gemm_core<false>(A, W, Kdim, Kdim, N, m0, n0, acc);

    EPI_LOOP(m0, n0, {
        val += bias ? bias[col] : 0.f;
        if (NH > 0) {
            int b = row / T;
            int t = row % T;
            int h = col >> 7;
            int d = col & 127;
            out[(((size_t)(b * NH + h)) * T + t) * D + d] = val;
        } else {
            out[(size_t)row * N + col] = val;
        }
    })
}

// ---------------------------------------------------------------------------
// Scores: S = SCALE * Q K^T + additive prefix-causal bias
// ---------------------------------------------------------------------------
__global__ void __launch_bounds__(256)
scores_mma(const float* __restrict__ q, const float* __restrict__ k,
           float* __restrict__ s)
{
    const int bh = blockIdx.z;
    const int b = bh / H, h = bh % H;
    const float* Q  = q + (size_t)(b * H + h) * T * D;
    const float* Kp = k + (size_t)(b * KV + h / GROUPS) * T * D;
    float* S = s + (size_t)bh * T * T;

    const int m0 = blockIdx.y * 128, n0 = blockIdx.x * 128;
    float acc[4][4][4] = {};
    gemm_core<true>(Q, Kp, D, D, D, m0, n0, acc);

    EPI_LOOP(m0, n0, {
        float bias = ((col < LP) || (row >= LP && col <= row)) ? 1.0f : 0.0f;
        S[(size_t)row * T + col] = val * SCALE + bias;
    })
}

// ---------------------------------------------------------------------------
// PV: O[b,t,h*D+d] = P @ V
// ---------------------------------------------------------------------------
__global__ void __launch_bounds__(256)
pv_mma(const float* __restrict__ s, const float* __restrict__ v,
       float* __restrict__ o)
{
    const int bh = blockIdx.z;
    const int b = bh / H, h = bh % H;
    const float* P = s + (size_t)bh * T * T;
    const float* V = v + (size_t)(b * KV + h / GROUPS) * T * D;

    const int m0 = blockIdx.y * 128, n0 = 0;
    float acc[4][4][4] = {};
    gemm_core<false>(P, V, T, T, D, m0, n0, acc);

    EPI_LOOP(m0, n0, {
        o[((size_t)b * T + row) * (H * D) + h * D + col] = val;
    })
}

// ---------------------------------------------------------------------------
// RoPE on [B,NH,T,D], positions t >= LP.
// ---------------------------------------------------------------------------
__global__ void __launch_bounds__(256)
rope_kernel(float* __restrict__ x, const float* __restrict__ cosp,
            const float* __restrict__ sinp, int NH)
{
    int idx = blockIdx.x * 256 + threadIdx.x;
    int d = idx & 63;
    int rest = idx >> 6;
    int t = rest % LSEQ + LP;
    int bh = rest / LSEQ;
    int b = bh / NH, h = bh % NH;

    size_t base  = ((size_t)(b * NH + h) * T + t) * D;
    size_t cbase = ((size_t)b * LSEQ + (t - LP)) * D;

    float x1 = x[base + d], x2 = x[base + d + 64];
    float c1 = cosp[cbase + d],      s1 = sinp[cbase + d];
    float c2 = cosp[cbase + d + 64], s2 = sinp[cbase + d + 64];
    x[base + d]      = x1 * c1 - x2 * s1;
    x[base + d + 64] = x2 * c2 + x1 * s2;
}

// ---------------------------------------------------------------------------
// Row softmax over T=2048. One block (256 thr) per row.
// ---------------------------------------------------------------------------
__global__ void __launch_bounds__(256)
softmax_rows(float* __restrict__ s)
{
    float* row = s + (size_t)blockIdx.x * T;
    __shared__ float red[256];
    int tid = threadIdx.x;

    float v[8];
    float mx = -1e30f;
#pragma unroll
    for (int i = 0; i < 8; i++) { v[i] = row[tid + i * 256]; mx = fmaxf(mx, v[i]); }
    red[tid] = mx; __syncthreads();
    for (int st = 128; st > 0; st >>= 1) {
        if (tid < st) red[tid] = fmaxf(red[tid], red[tid + st]);
        __syncthreads();
    }
    mx = red[0]; __syncthreads();

    float sum = 0.f;
#pragma unroll
    for (int i = 0; i < 8; i++) { v[i] = __expf(v[i] - mx); sum += v[i]; }
    red[tid] = sum; __syncthreads();
    for (int st = 128; st > 0; st >>= 1) {
        if (tid < st) red[tid] += red[tid + st];
        __syncthreads();
    }
    float inv = 1.0f / red[0];
#pragma unroll
    for (int i = 0; i < 8; i++) row[tid + i * 256] = v[i] * inv;
}

// ---------------------------------------------------------------------------
// Launch
// ---------------------------------------------------------------------------
extern "C" void kernel_launch(void* const* d_in, const int* in_sizes, int n_in,
                              void* d_out, int out_size)
{
    (void)in_sizes; (void)n_in; (void)out_size;
    const float* hs   = (const float*)d_in[0];
    const float* cosp = (const float*)d_in[1];
    const float* sinp = (const float*)d_in[2];
    const float* Wq   = (const float*)d_in[3];
    const float* bq   = (const float*)d_in[4];
    const float* Wk   = (const float*)d_in[5];
    const float* bk   = (const float*)d_in[6];
    const float* Wv   = (const float*)d_in[7];
    const float* bv   = (const float*)d_in[8];
    const float* Wo   = (const float*)d_in[9];
    float* out = (float*)d_out;

    float *q, *k, *v, *s, *o;
    cudaGetSymbolAddress((void**)&q, g_q);
    cudaGetSymbolAddress((void**)&k, g_k);
    cudaGetSymbolAddress((void**)&v, g_v);
    cudaGetSymbolAddress((void**)&s, g_s);
    cudaGetSymbolAddress((void**)&o, g_o);

    const int M = B * T;  // 4096

    // QKV projections (tensor cores, scatter to [B,heads,T,D])
    proj_mma<<<dim3((H * D) / 128, M / 128), 256>>>(hs, Wq, bq, q, H * D, C, H);
    proj_mma<<<dim3((KV * D) / 128, M / 128), 256>>>(hs, Wk, bk, k, KV * D, C, KV);
    proj_mma<<<dim3((KV * D) / 128, M / 128), 256>>>(hs, Wv, bv, v, KV * D, C, KV);

    // RoPE
    rope_kernel<<<(B * H * LSEQ * 64) / 256, 256>>>(q, cosp, sinp, H);
    rope_kernel<<<(B * KV * LSEQ * 64) / 256, 256>>>(k, cosp, sinp, KV);

    // Scores
    scores_mma<<<dim3(T / 128, T / 128, B * H), 256>>>(q, k, s);

    // Softmax
    softmax_rows<<<B * H * T, 256>>>(s);

    // PV
    pv_mma<<<dim3(1, T / 128, B * H), 256>>>(s, v, o);

    // Output projection
    proj_mma<<<dim3(C / 128, M / 128), 256>>>(o, Wo, nullptr, out, C, H * D, 0);
}

// round 7
// speedup vs baseline: 1.2459x; 1.2459x over previous
#include <cuda_runtime.h>
#include <cuda_bf16.h>
#include <math.h>
#include <stdint.h>

#define B   2
#define T   2048
#define C   2048
#define H   16
#define KV  4
#define D   128
#define LP  64
#define GROUPS (H / KV)
#define LSEQ (T - LP)            // 1984
#define SCALE 0.08838834764831845f   // 1/sqrt(128)

// ---------------- scratch (static device globals: allowed) ----------------
__device__ float g_q[(size_t)B * H * T * D];          // [B,H,T,D]
__device__ float g_k[(size_t)B * KV * T * D];         // [B,KV,T,D]
__device__ float g_v[(size_t)B * KV * T * D];         // [B,KV,T,D]
__device__ float g_o[(size_t)B * T * H * D];          // [B,T,H*D]

// ---------------------------------------------------------------------------
// tf32 helpers
// ---------------------------------------------------------------------------
__device__ __forceinline__ uint32_t f2tf(float x) {
    uint32_t r;
    asm("cvt.rna.tf32.f32 %0, %1;" : "=r"(r) : "f"(x));
    return r;
}

__device__ __forceinline__ float2 split_tf32(float x) {
    uint32_t hi = f2tf(x);
    uint32_t lo = f2tf(x - __uint_as_float(hi));
    float2 p;
    p.x = __uint_as_float(hi);
    p.y = __uint_as_float(lo);
    return p;
}

__device__ __forceinline__ void mma_tf32(float c[4],
                                         const uint32_t a[4],
                                         const uint32_t b[2]) {
    asm volatile(
        "mma.sync.aligned.m16n8k8.row.col.f32.tf32.tf32.f32 "
        "{%0,%1,%2,%3},{%4,%5,%6,%7},{%8,%9},{%0,%1,%2,%3};"
        : "+f"(c[0]), "+f"(c[1]), "+f"(c[2]), "+f"(c[3])
        : "r"(a[0]), "r"(a[1]), "r"(a[2]), "r"(a[3]), "r"(b[0]), "r"(b[1]));
}

// ===========================================================================
// R5 GEMM core (register-side split) — proven, used for all projections.
// ===========================================================================
template<bool TRANSB>
__device__ __forceinline__ void gemm_core(const float* __restrict__ A,
                                          const float* __restrict__ Bm,
                                          int Kdim, int lda, int ldb,
                                          int m0, int n0,
                                          float acc[4][4][4])
{
    __shared__ float As[16][136];
    __shared__ float Bs[16][136];

    const int tid  = threadIdx.x;
    const int lane = tid & 31;
    const int warp = tid >> 5;
    const int gid  = lane >> 2;
    const int tig  = lane & 3;
    const int wm   = (warp >> 2) * 64;
    const int wn   = (warp & 3) * 32;

    const int ar  = tid >> 2;
    const int ac4 = (tid & 3) * 4;
    const int br  = tid >> 4;
    const int bc  = (tid & 15) * 4;

    for (int k0 = 0; k0 < Kdim; k0 += 16) {
#pragma unroll
        for (int half = 0; half < 2; half++) {
            int row = ar + half * 64;
            float4 v = *reinterpret_cast<const float4*>(
                &A[(size_t)(m0 + row) * lda + k0 + ac4]);
            As[ac4 + 0][row] = v.x; As[ac4 + 1][row] = v.y;
            As[ac4 + 2][row] = v.z; As[ac4 + 3][row] = v.w;
        }
        if (TRANSB) {
#pragma unroll
            for (int half = 0; half < 2; half++) {
                int row = ar + half * 64;
                float4 v = *reinterpret_cast<const float4*>(
                    &Bm[(size_t)(n0 + row) * ldb + k0 + ac4]);
                Bs[ac4 + 0][row] = v.x; Bs[ac4 + 1][row] = v.y;
                Bs[ac4 + 2][row] = v.z; Bs[ac4 + 3][row] = v.w;
            }
        } else {
#pragma unroll
            for (int half = 0; half < 2; half++) {
                *reinterpret_cast<float4*>(&Bs[br][bc + half * 64]) =
                    *reinterpret_cast<const float4*>(
                        &Bm[(size_t)(k0 + br) * ldb + n0 + bc + half * 64]);
            }
        }
        __syncthreads();

#pragma unroll
        for (int ks = 0; ks < 2; ks++) {
            uint32_t ahi[4][4], alo[4][4];
#pragma unroll
            for (int mf = 0; mf < 4; mf++)
#pragma unroll
                for (int r = 0; r < 4; r++) {
                    int krow = ks * 8 + tig + (r >> 1) * 4;
                    int mcol = wm + mf * 16 + gid + (r & 1) * 8;
                    float a = As[krow][mcol];
                    uint32_t hi = f2tf(a);
                    ahi[mf][r] = hi;
                    alo[mf][r] = f2tf(a - __uint_as_float(hi));
                }
            uint32_t bhi[4][2], blo[4][2];
#pragma unroll
            for (int nf = 0; nf < 4; nf++)
#pragma unroll
                for (int r = 0; r < 2; r++) {
                    int krow = ks * 8 + tig + r * 4;
                    int ncol = wn + nf * 8 + gid;
                    float b = Bs[krow][ncol];
                    uint32_t hi = f2tf(b);
                    bhi[nf][r] = hi;
                    blo[nf][r] = f2tf(b - __uint_as_float(hi));
                }
#pragma unroll
            for (int mf = 0; mf < 4; mf++)
#pragma unroll
                for (int nf = 0; nf < 4; nf++) {
                    mma_tf32(acc[mf][nf], ahi[mf], bhi[nf]);
                    mma_tf32(acc[mf][nf], ahi[mf], blo[nf]);
                    mma_tf32(acc[mf][nf], alo[mf], bhi[nf]);
                }
        }
        __syncthreads();
    }
}

#define EPI_LOOP(ROW_EXPR, COL_EXPR, ...)                                    \
    {                                                                        \
        const int lane = threadIdx.x & 31;                                   \
        const int warp = threadIdx.x >> 5;                                   \
        const int gid = lane >> 2, tig = lane & 3;                           \
        const int wm = (warp >> 2) * 64, wn = (warp & 3) * 32;               \
        _Pragma("unroll") for (int mf = 0; mf < 4; mf++)                     \
        _Pragma("unroll") for (int nf = 0; nf < 4; nf++)                     \
        _Pragma("unroll") for (int r = 0; r < 4; r++) {                      \
            int row = (ROW_EXPR) + wm + mf * 16 + gid + ((r >> 1) * 8);      \
            int col = (COL_EXPR) + wn + nf * 8 + tig * 2 + (r & 1);          \
            float val = acc[mf][nf][r];                                      \
            __VA_ARGS__                                                      \
        }                                                                    \
    }

__global__ void __launch_bounds__(256)
proj_mma(const float* __restrict__ A, const float* __restrict__ W,
         const float* __restrict__ bias, float* __restrict__ out,
         int N, int Kdim, int NH)
{
    const int m0 = blockIdx.y * 128, n0 = blockIdx.x * 128;
    float acc[4][4][4] = {};
    gemm_core<false>(A, W, Kdim, Kdim, N, m0, n0, acc);

    EPI_LOOP(m0, n0, {
        val += bias ? bias[col] : 0.f;
        if (NH > 0) {
            int b = row / T;
            int t = row % T;
            int h = col >> 7;
            int d = col & 127;
            out[(((size_t)(b * NH + h)) * T + t) * D + d] = val;
        } else {
            out[(size_t)row * N + col] = val;
        }
    })
}

// ===========================================================================
// Fused flash attention: scores + online softmax + PV in one kernel.
// Block: 256 threads (8 warps), Q tile = 128 rows (warp w owns rows w*16..+16).
// KV processed in tiles of 32 keys. All smem operands stored as split
// tf32 (hi,lo) float2 with pitch ≡ 4 mod 16 f2 → conflict-free frag reads.
// ===========================================================================
#define KTILE 32
#define NTILES (T / KTILE)   // 64
#define QP 132               // f2 pitch, [128 d][m]
#define KP 36                // f2 pitch, [128 d][key^swz]
#define VP 132               // f2 pitch, [32 key][d]
#define PP 132               // f2 pitch, [32 key][m]
#define FLASH_SMEM ((128 * QP + 128 * KP + KTILE * PP) * sizeof(float2))

__global__ void __launch_bounds__(256, 1)
flash_attn(const float* __restrict__ q, const float* __restrict__ k,
           const float* __restrict__ v, float* __restrict__ o)
{
    extern __shared__ float2 sm[];
    float2* Qs  = sm;                       // [d][m]
    float2* KVs = sm + 128 * QP;            // K: [d][key^swz]  /  V: [key][d]
    float2* Ps  = KVs + 128 * KP;           // [key][m]

    const int tid  = threadIdx.x;
    const int lane = tid & 31, warp = tid >> 5;
    const int gid  = lane >> 2, tig = lane & 3;
    const int w16  = warp * 16;

    const int m0 = blockIdx.x * 128;
    const int bh = blockIdx.y;
    const int b  = bh / H, h = bh % H;

    const float* Qg = q + ((size_t)(b * H + h) * T + m0) * D;
    const float* Kg = k + (size_t)(b * KV + h / GROUPS) * T * D;
    const float* Vg = v + (size_t)(b * KV + h / GROUPS) * T * D;

    // ---- load Q tile once, split, store transposed [d][m] ----
    {
        int row = tid >> 1;
#pragma unroll
        for (int j = 0; j < 16; j++) {
            int d4 = (tid & 1) * 4 + j * 8;
            float4 qv = *reinterpret_cast<const float4*>(&Qg[(size_t)row * D + d4]);
            Qs[(d4 + 0) * QP + row] = split_tf32(qv.x);
            Qs[(d4 + 1) * QP + row] = split_tf32(qv.y);
            Qs[(d4 + 2) * QP + row] = split_tf32(qv.z);
            Qs[(d4 + 3) * QP + row] = split_tf32(qv.w);
        }
    }

    float o_acc[16][4];
#pragma unroll
    for (int nf = 0; nf < 16; nf++)
#pragma unroll
        for (int r = 0; r < 4; r++) o_acc[nf][r] = 0.f;
    float m_i[2] = {-1e30f, -1e30f};
    float l_i[2] = {0.f, 0.f};

    for (int tile = 0; tile < NTILES; tile++) {
        const int kt0 = tile * KTILE;
        __syncthreads();   // prev PV reads of KVs done

        // ---- load K tile -> KVs[d][key ^ ((d>>2)&7)] ----
        {
            int key = tid >> 3;
            int swz = tid & 7;               // = ((d4+i)>>2)&7 for all i<4
            int kcol = key ^ swz;
#pragma unroll
            for (int j = 0; j < 4; j++) {
                int d4 = (tid & 7) * 4 + j * 32;
                float4 kv = *reinterpret_cast<const float4*>(
                    &Kg[(size_t)(kt0 + key) * D + d4]);
                KVs[(d4 + 0) * KP + kcol] = split_tf32(kv.x);
                KVs[(d4 + 1) * KP + kcol] = split_tf32(kv.y);
                KVs[(d4 + 2) * KP + kcol] = split_tf32(kv.z);
                KVs[(d4 + 3) * KP + kcol] = split_tf32(kv.w);
            }
        }
        __syncthreads();

        // ---- S = Q K^T (3x tf32), warp tile 16 rows x 32 keys ----
        float s[4][4];
#pragma unroll
        for (int nf = 0; nf < 4; nf++)
#pragma unroll
            for (int r = 0; r < 4; r++) s[nf][r] = 0.f;

#pragma unroll
        for (int ks = 0; ks < 16; ks++) {
            uint32_t ahi[4], alo[4];
#pragma unroll
            for (int r = 0; r < 4; r++) {
                float2 p = Qs[(ks * 8 + tig + (r >> 1) * 4) * QP
                              + (w16 + gid + (r & 1) * 8)];
                ahi[r] = __float_as_uint(p.x);
                alo[r] = __float_as_uint(p.y);
            }
            const int swz0 = (2 * ks) & 7;
            const int swz1 = (2 * ks + 1) & 7;
#pragma unroll
            for (int nf = 0; nf < 4; nf++) {
                float2 p0 = KVs[(ks * 8 + tig) * KP + ((nf * 8 + gid) ^ swz0)];
                float2 p1 = KVs[(ks * 8 + tig + 4) * KP + ((nf * 8 + gid) ^ swz1)];
                uint32_t bhi[2] = {__float_as_uint(p0.x), __float_as_uint(p1.x)};
                uint32_t blo[2] = {__float_as_uint(p0.y), __float_as_uint(p1.y)};
                mma_tf32(s[nf], ahi, bhi);
                mma_tf32(s[nf], ahi, blo);
                mma_tf32(s[nf], alo, bhi);
            }
        }

        // ---- bias + scale + online softmax (rows warp-local) ----
        float mx[2] = {-1e30f, -1e30f};
#pragma unroll
        for (int nf = 0; nf < 4; nf++)
#pragma unroll
            for (int r = 0; r < 4; r++) {
                int j = kt0 + nf * 8 + tig * 2 + (r & 1);
                int qrow = m0 + w16 + gid + (r >> 1) * 8;
                float bias = ((j < LP) || (qrow >= LP && j <= qrow)) ? 1.0f : 0.0f;
                float val = s[nf][r] * SCALE + bias;
                s[nf][r] = val;
                mx[r >> 1] = fmaxf(mx[r >> 1], val);
            }
        float sf[2];
#pragma unroll
        for (int r01 = 0; r01 < 2; r01++) {
            float m = mx[r01];
            m = fmaxf(m, __shfl_xor_sync(0xffffffffu, m, 1));
            m = fmaxf(m, __shfl_xor_sync(0xffffffffu, m, 2));
            float m_new = fmaxf(m_i[r01], m);
            sf[r01] = __expf(m_i[r01] - m_new);
            m_i[r01] = m_new;
        }
        float sum[2] = {0.f, 0.f};
#pragma unroll
        for (int nf = 0; nf < 4; nf++)
#pragma unroll
            for (int r = 0; r < 4; r++) {
                float p = __expf(s[nf][r] - m_i[r >> 1]);
                sum[r >> 1] += p;
                Ps[(nf * 8 + tig * 2 + (r & 1)) * PP
                   + (w16 + gid + (r >> 1) * 8)] = split_tf32(p);
            }
#pragma unroll
        for (int r01 = 0; r01 < 2; r01++) {
            float ssum = sum[r01];
            ssum += __shfl_xor_sync(0xffffffffu, ssum, 1);
            ssum += __shfl_xor_sync(0xffffffffu, ssum, 2);
            l_i[r01] = l_i[r01] * sf[r01] + ssum;
        }
#pragma unroll
        for (int nf = 0; nf < 16; nf++)
#pragma unroll
            for (int r = 0; r < 4; r++) o_acc[nf][r] *= sf[r >> 1];

        __syncthreads();   // all warps done reading K

        // ---- load V tile -> KVs[key][d] ----
        {
            int key = tid >> 3;
#pragma unroll
            for (int j = 0; j < 4; j++) {
                int d4 = (tid & 7) * 4 + j * 32;
                float4 vv = *reinterpret_cast<const float4*>(
                    &Vg[(size_t)(kt0 + key) * D + d4]);
                KVs[key * VP + d4 + 0] = split_tf32(vv.x);
                KVs[key * VP + d4 + 1] = split_tf32(vv.y);
                KVs[key * VP + d4 + 2] = split_tf32(vv.z);
                KVs[key * VP + d4 + 3] = split_tf32(vv.w);
            }
        }
        __syncthreads();

        // ---- O += P V (3x tf32), k-dim = 32 keys ----
#pragma unroll
        for (int ks = 0; ks < 4; ks++) {
            uint32_t ahi[4], alo[4];
#pragma unroll
            for (int r = 0; r < 4; r++) {
                float2 p = Ps[(ks * 8 + tig + (r >> 1) * 4) * PP
                              + (w16 + gid + (r & 1) * 8)];
                ahi[r] = __float_as_uint(p.x);
                alo[r] = __float_as_uint(p.y);
            }
#pragma unroll
            for (int nf = 0; nf < 16; nf++) {
                float2 p0 = KVs[(ks * 8 + tig) * VP + nf * 8 + gid];
                float2 p1 = KVs[(ks * 8 + tig + 4) * VP + nf * 8 + gid];
                uint32_t bhi[2] = {__float_as_uint(p0.x), __float_as_uint(p1.x)};
                uint32_t blo[2] = {__float_as_uint(p0.y), __float_as_uint(p1.y)};
                mma_tf32(o_acc[nf], ahi, bhi);
                mma_tf32(o_acc[nf], ahi, blo);
                mma_tf32(o_acc[nf], alo, bhi);
            }
        }
    }

    // ---- epilogue: O /= l, write [B,T,H*D] ----
    float inv[2] = {1.f / l_i[0], 1.f / l_i[1]};
#pragma unroll
    for (int nf = 0; nf < 16; nf++)
#pragma unroll
        for (int r01 = 0; r01 < 2; r01++) {
            int qrow = m0 + w16 + gid + r01 * 8;
            int dcol = nf * 8 + tig * 2;
            float2 ov;
            ov.x = o_acc[nf][r01 * 2 + 0] * inv[r01];
            ov.y = o_acc[nf][r01 * 2 + 1] * inv[r01];
            *reinterpret_cast<float2*>(
                &o[((size_t)b * T + qrow) * (H * D) + h * D + dcol]) = ov;
        }
}

// ---------------------------------------------------------------------------
// RoPE on [B,NH,T,D], positions t >= LP.
// ---------------------------------------------------------------------------
__global__ void __launch_bounds__(256)
rope_kernel(float* __restrict__ x, const float* __restrict__ cosp,
            const float* __restrict__ sinp, int NH)
{
    int idx = blockIdx.x * 256 + threadIdx.x;
    int d = idx & 63;
    int rest = idx >> 6;
    int t = rest % LSEQ + LP;
    int bh = rest / LSEQ;
    int b = bh / NH, h = bh % NH;

    size_t base  = ((size_t)(b * NH + h) * T + t) * D;
    size_t cbase = ((size_t)b * LSEQ + (t - LP)) * D;

    float x1 = x[base + d], x2 = x[base + d + 64];
    float c1 = cosp[cbase + d],      s1 = sinp[cbase + d];
    float c2 = cosp[cbase + d + 64], s2 = sinp[cbase + d + 64];
    x[base + d]      = x1 * c1 - x2 * s1;
    x[base + d + 64] = x2 * c2 + x1 * s2;
}

// ---------------------------------------------------------------------------
// Launch
// ---------------------------------------------------------------------------
extern "C" void kernel_launch(void* const* d_in, const int* in_sizes, int n_in,
                              void* d_out, int out_size)
{
    (void)in_sizes; (void)n_in; (void)out_size;
    const float* hs   = (const float*)d_in[0];
    const float* cosp = (const float*)d_in[1];
    const float* sinp = (const float*)d_in[2];
    const float* Wq   = (const float*)d_in[3];
    const float* bq   = (const float*)d_in[4];
    const float* Wk   = (const float*)d_in[5];
    const float* bk   = (const float*)d_in[6];
    const float* Wv   = (const float*)d_in[7];
    const float* bv   = (const float*)d_in[8];
    const float* Wo   = (const float*)d_in[9];
    float* out = (float*)d_out;

    float *q, *k, *v, *o;
    cudaGetSymbolAddress((void**)&q, g_q);
    cudaGetSymbolAddress((void**)&k, g_k);
    cudaGetSymbolAddress((void**)&v, g_v);
    cudaGetSymbolAddress((void**)&o, g_o);

    cudaFuncSetAttribute(flash_attn,
                         cudaFuncAttributeMaxDynamicSharedMemorySize,
                         (int)FLASH_SMEM);

    const int M = B * T;  // 4096

    // QKV projections (tensor cores, scatter to [B,heads,T,D])
    proj_mma<<<dim3((H * D) / 128, M / 128), 256>>>(hs, Wq, bq, q, H * D, C, H);
    proj_mma<<<dim3((KV * D) / 128, M / 128), 256>>>(hs, Wk, bk, k, KV * D, C, KV);
    proj_mma<<<dim3((KV * D) / 128, M / 128), 256>>>(hs, Wv, bv, v, KV * D, C, KV);

    // RoPE
    rope_kernel<<<(B * H * LSEQ * 64) / 256, 256>>>(q, cosp, sinp, H);
    rope_kernel<<<(B * KV * LSEQ * 64) / 256, 256>>>(k, cosp, sinp, KV);

    // Fused attention (scores + softmax + PV)
    flash_attn<<<dim3(T / 128, B * H), 256, FLASH_SMEM>>>(q, k, v, o);

    // Output projection
    proj_mma<<<dim3(C / 128, M / 128), 256>>>(o, Wo, nullptr, out, C, H * D, 0);
}

// round 8
// speedup vs baseline: 1.2465x; 1.0005x over previous
#include <cuda_runtime.h>
#include <cuda_bf16.h>
#include <math.h>
#include <stdint.h>

#define B   2
#define T   2048
#define C   2048
#define H   16
#define KV  4
#define D   128
#define LP  64
#define GROUPS (H / KV)
#define LSEQ (T - LP)            // 1984
#define SCALE 0.08838834764831845f   // 1/sqrt(128)

// ---------------- scratch (static device globals: allowed) ----------------
__device__ float g_q[(size_t)B * H * T * D];          // [B,H,T,D]
__device__ float g_k[(size_t)B * KV * T * D];         // [B,KV,T,D]
__device__ float g_v[(size_t)B * KV * T * D];         // [B,KV,T,D]
__device__ float g_o[(size_t)B * T * H * D];          // [B,T,H*D]

// ---------------------------------------------------------------------------
// tf32 helpers
// ---------------------------------------------------------------------------
__device__ __forceinline__ uint32_t f2tf(float x) {
    uint32_t r;
    asm("cvt.rna.tf32.f32 %0, %1;" : "=r"(r) : "f"(x));
    return r;
}

__device__ __forceinline__ float2 split_tf32(float x) {
    uint32_t hi = f2tf(x);
    uint32_t lo = f2tf(x - __uint_as_float(hi));
    float2 p;
    p.x = __uint_as_float(hi);
    p.y = __uint_as_float(lo);
    return p;
}

__device__ __forceinline__ void mma_tf32(float c[4],
                                         const uint32_t a[4],
                                         const uint32_t b[2]) {
    asm volatile(
        "mma.sync.aligned.m16n8k8.row.col.f32.tf32.tf32.f32 "
        "{%0,%1,%2,%3},{%4,%5,%6,%7},{%8,%9},{%0,%1,%2,%3};"
        : "+f"(c[0]), "+f"(c[1]), "+f"(c[2]), "+f"(c[3])
        : "r"(a[0]), "r"(a[1]), "r"(a[2]), "r"(a[3]), "r"(b[0]), "r"(b[1]));
}

// ===========================================================================
// R5 GEMM core (register-side split) — proven, used for all projections.
// ===========================================================================
template<bool TRANSB>
__device__ __forceinline__ void gemm_core(const float* __restrict__ A,
                                          const float* __restrict__ Bm,
                                          int Kdim, int lda, int ldb,
                                          int m0, int n0,
                                          float acc[4][4][4])
{
    __shared__ float As[16][136];
    __shared__ float Bs[16][136];

    const int tid  = threadIdx.x;
    const int lane = tid & 31;
    const int warp = tid >> 5;
    const int gid  = lane >> 2;
    const int tig  = lane & 3;
    const int wm   = (warp >> 2) * 64;
    const int wn   = (warp & 3) * 32;

    const int ar  = tid >> 2;
    const int ac4 = (tid & 3) * 4;
    const int br  = tid >> 4;
    const int bc  = (tid & 15) * 4;

    for (int k0 = 0; k0 < Kdim; k0 += 16) {
#pragma unroll
        for (int half = 0; half < 2; half++) {
            int row = ar + half * 64;
            float4 v = *reinterpret_cast<const float4*>(
                &A[(size_t)(m0 + row) * lda + k0 + ac4]);
            As[ac4 + 0][row] = v.x; As[ac4 + 1][row] = v.y;
            As[ac4 + 2][row] = v.z; As[ac4 + 3][row] = v.w;
        }
        if (TRANSB) {
#pragma unroll
            for (int half = 0; half < 2; half++) {
                int row = ar + half * 64;
                float4 v = *reinterpret_cast<const float4*>(
                    &Bm[(size_t)(n0 + row) * ldb + k0 + ac4]);
                Bs[ac4 + 0][row] = v.x; Bs[ac4 + 1][row] = v.y;
                Bs[ac4 + 2][row] = v.z; Bs[ac4 + 3][row] = v.w;
            }
        } else {
#pragma unroll
            for (int half = 0; half < 2; half++) {
                *reinterpret_cast<float4*>(&Bs[br][bc + half * 64]) =
                    *reinterpret_cast<const float4*>(
                        &Bm[(size_t)(k0 + br) * ldb + n0 + bc + half * 64]);
            }
        }
        __syncthreads();

#pragma unroll
        for (int ks = 0; ks < 2; ks++) {
            uint32_t ahi[4][4], alo[4][4];
#pragma unroll
            for (int mf = 0; mf < 4; mf++)
#pragma unroll
                for (int r = 0; r < 4; r++) {
                    int krow = ks * 8 + tig + (r >> 1) * 4;
                    int mcol = wm + mf * 16 + gid + (r & 1) * 8;
                    float a = As[krow][mcol];
                    uint32_t hi = f2tf(a);
                    ahi[mf][r] = hi;
                    alo[mf][r] = f2tf(a - __uint_as_float(hi));
                }
            uint32_t bhi[4][2], blo[4][2];
#pragma unroll
            for (int nf = 0; nf < 4; nf++)
#pragma unroll
                for (int r = 0; r < 2; r++) {
                    int krow = ks * 8 + tig + r * 4;
                    int ncol = wn + nf * 8 + gid;
                    float b = Bs[krow][ncol];
                    uint32_t hi = f2tf(b);
                    bhi[nf][r] = hi;
                    blo[nf][r] = f2tf(b - __uint_as_float(hi));
                }
#pragma unroll
            for (int mf = 0; mf < 4; mf++)
#pragma unroll
                for (int nf = 0; nf < 4; nf++) {
                    mma_tf32(acc[mf][nf], ahi[mf], bhi[nf]);
                    mma_tf32(acc[mf][nf], ahi[mf], blo[nf]);
                    mma_tf32(acc[mf][nf], alo[mf], bhi[nf]);
                }
        }
        __syncthreads();
    }
}

#define EPI_LOOP(ROW_EXPR, COL_EXPR, ...)                                    \
    {                                                                        \
        const int lane = threadIdx.x & 31;                                   \
        const int warp = threadIdx.x >> 5;                                   \
        const int gid = lane >> 2, tig = lane & 3;                           \
        const int wm = (warp >> 2) * 64, wn = (warp & 3) * 32;               \
        _Pragma("unroll") for (int mf = 0; mf < 4; mf++)                     \
        _Pragma("unroll") for (int nf = 0; nf < 4; nf++)                     \
        _Pragma("unroll") for (int r = 0; r < 4; r++) {                      \
            int row = (ROW_EXPR) + wm + mf * 16 + gid + ((r >> 1) * 8);      \
            int col = (COL_EXPR) + wn + nf * 8 + tig * 2 + (r & 1);          \
            float val = acc[mf][nf][r];                                      \
            __VA_ARGS__                                                      \
        }                                                                    \
    }

__global__ void __launch_bounds__(256)
proj_mma(const float* __restrict__ A, const float* __restrict__ W,
         const float* __restrict__ bias, float* __restrict__ out,
         int N, int Kdim, int NH)
{
    const int m0 = blockIdx.y * 128, n0 = blockIdx.x * 128;
    float acc[4][4][4] = {};
    gemm_core<false>(A, W, Kdim, Kdim, N, m0, n0, acc);

    EPI_LOOP(m0, n0, {
        val += bias ? bias[col] : 0.f;
        if (NH > 0) {
            int b = row / T;
            int t = row % T;
            int h = col >> 7;
            int d = col & 127;
            out[(((size_t)(b * NH + h)) * T + t) * D + d] = val;
        } else {
            out[(size_t)row * N + col] = val;
        }
    })
}

// ===========================================================================
// Fused flash attention: scores + online softmax + PV in one kernel.
// Block: 256 threads (8 warps), Q tile = 128 rows (warp w owns rows w*16..+16).
// KV processed in tiles of 32 keys. All smem operands stored as split
// tf32 (hi,lo) float2 with pitch ≡ 4 mod 16 f2 → conflict-free frag reads.
// ===========================================================================
#define KTILE 32
#define NTILES (T / KTILE)   // 64
#define QP 132               // f2 pitch, [128 d][m]
#define KP 36                // f2 pitch, [128 d][key^swz]
#define VP 132               // f2 pitch, [32 key][d]
#define PP 132               // f2 pitch, [32 key][m]
#define FLASH_SMEM ((128 * QP + 128 * KP + KTILE * PP) * sizeof(float2))

__global__ void __launch_bounds__(256, 1)
flash_attn(const float* __restrict__ q, const float* __restrict__ k,
           const float* __restrict__ v, float* __restrict__ o)
{
    extern __shared__ float2 sm[];
    float2* Qs  = sm;                       // [d][m]
    float2* KVs = sm + 128 * QP;            // K: [d][key^swz]  /  V: [key][d]
    float2* Ps  = KVs + 128 * KP;           // [key][m]

    const int tid  = threadIdx.x;
    const int lane = tid & 31, warp = tid >> 5;
    const int gid  = lane >> 2, tig = lane & 3;
    const int w16  = warp * 16;

    const int m0 = blockIdx.x * 128;
    const int bh = blockIdx.y;
    const int b  = bh / H, h = bh % H;

    const float* Qg = q + ((size_t)(b * H + h) * T + m0) * D;
    const float* Kg = k + (size_t)(b * KV + h / GROUPS) * T * D;
    const float* Vg = v + (size_t)(b * KV + h / GROUPS) * T * D;

    // ---- load Q tile once, split, store transposed [d][m] ----
    {
        int row = tid >> 1;
#pragma unroll
        for (int j = 0; j < 16; j++) {
            int d4 = (tid & 1) * 4 + j * 8;
            float4 qv = *reinterpret_cast<const float4*>(&Qg[(size_t)row * D + d4]);
            Qs[(d4 + 0) * QP + row] = split_tf32(qv.x);
            Qs[(d4 + 1) * QP + row] = split_tf32(qv.y);
            Qs[(d4 + 2) * QP + row] = split_tf32(qv.z);
            Qs[(d4 + 3) * QP + row] = split_tf32(qv.w);
        }
    }

    float o_acc[16][4];
#pragma unroll
    for (int nf = 0; nf < 16; nf++)
#pragma unroll
        for (int r = 0; r < 4; r++) o_acc[nf][r] = 0.f;
    float m_i[2] = {-1e30f, -1e30f};
    float l_i[2] = {0.f, 0.f};

    for (int tile = 0; tile < NTILES; tile++) {
        const int kt0 = tile * KTILE;
        __syncthreads();   // prev PV reads of KVs done

        // ---- load K tile -> KVs[d][key ^ ((d>>2)&7)] ----
        {
            int key = tid >> 3;
            int swz = tid & 7;               // = ((d4+i)>>2)&7 for all i<4
            int kcol = key ^ swz;
#pragma unroll
            for (int j = 0; j < 4; j++) {
                int d4 = (tid & 7) * 4 + j * 32;
                float4 kv = *reinterpret_cast<const float4*>(
                    &Kg[(size_t)(kt0 + key) * D + d4]);
                KVs[(d4 + 0) * KP + kcol] = split_tf32(kv.x);
                KVs[(d4 + 1) * KP + kcol] = split_tf32(kv.y);
                KVs[(d4 + 2) * KP + kcol] = split_tf32(kv.z);
                KVs[(d4 + 3) * KP + kcol] = split_tf32(kv.w);
            }
        }
        __syncthreads();

        // ---- S = Q K^T (3x tf32), warp tile 16 rows x 32 keys ----
        float s[4][4];
#pragma unroll
        for (int nf = 0; nf < 4; nf++)
#pragma unroll
            for (int r = 0; r < 4; r++) s[nf][r] = 0.f;

#pragma unroll
        for (int ks = 0; ks < 16; ks++) {
            uint32_t ahi[4], alo[4];
#pragma unroll
            for (int r = 0; r < 4; r++) {
                float2 p = Qs[(ks * 8 + tig + (r >> 1) * 4) * QP
                              + (w16 + gid + (r & 1) * 8)];
                ahi[r] = __float_as_uint(p.x);
                alo[r] = __float_as_uint(p.y);
            }
            const int swz0 = (2 * ks) & 7;
            const int swz1 = (2 * ks + 1) & 7;
#pragma unroll
            for (int nf = 0; nf < 4; nf++) {
                float2 p0 = KVs[(ks * 8 + tig) * KP + ((nf * 8 + gid) ^ swz0)];
                float2 p1 = KVs[(ks * 8 + tig + 4) * KP + ((nf * 8 + gid) ^ swz1)];
                uint32_t bhi[2] = {__float_as_uint(p0.x), __float_as_uint(p1.x)};
                uint32_t blo[2] = {__float_as_uint(p0.y), __float_as_uint(p1.y)};
                mma_tf32(s[nf], ahi, bhi);
                mma_tf32(s[nf], ahi, blo);
                mma_tf32(s[nf], alo, bhi);
            }
        }

        // ---- bias + scale + online softmax (rows warp-local) ----
        float mx[2] = {-1e30f, -1e30f};
#pragma unroll
        for (int nf = 0; nf < 4; nf++)
#pragma unroll
            for (int r = 0; r < 4; r++) {
                int j = kt0 + nf * 8 + tig * 2 + (r & 1);
                int qrow = m0 + w16 + gid + (r >> 1) * 8;
                float bias = ((j < LP) || (qrow >= LP && j <= qrow)) ? 1.0f : 0.0f;
                float val = s[nf][r] * SCALE + bias;
                s[nf][r] = val;
                mx[r >> 1] = fmaxf(mx[r >> 1], val);
            }
        float sf[2];
#pragma unroll
        for (int r01 = 0; r01 < 2; r01++) {
            float m = mx[r01];
            m = fmaxf(m, __shfl_xor_sync(0xffffffffu, m, 1));
            m = fmaxf(m, __shfl_xor_sync(0xffffffffu, m, 2));
            float m_new = fmaxf(m_i[r01], m);
            sf[r01] = __expf(m_i[r01] - m_new);
            m_i[r01] = m_new;
        }
        float sum[2] = {0.f, 0.f};
#pragma unroll
        for (int nf = 0; nf < 4; nf++)
#pragma unroll
            for (int r = 0; r < 4; r++) {
                float p = __expf(s[nf][r] - m_i[r >> 1]);
                sum[r >> 1] += p;
                Ps[(nf * 8 + tig * 2 + (r & 1)) * PP
                   + (w16 + gid + (r >> 1) * 8)] = split_tf32(p);
            }
#pragma unroll
        for (int r01 = 0; r01 < 2; r01++) {
            float ssum = sum[r01];
            ssum += __shfl_xor_sync(0xffffffffu, ssum, 1);
            ssum += __shfl_xor_sync(0xffffffffu, ssum, 2);
            l_i[r01] = l_i[r01] * sf[r01] + ssum;
        }
#pragma unroll
        for (int nf = 0; nf < 16; nf++)
#pragma unroll
            for (int r = 0; r < 4; r++) o_acc[nf][r] *= sf[r >> 1];

        __syncthreads();   // all warps done reading K

        // ---- load V tile -> KVs[key][d] ----
        {
            int key = tid >> 3;
#pragma unroll
            for (int j = 0; j < 4; j++) {
                int d4 = (tid & 7) * 4 + j * 32;
                float4 vv = *reinterpret_cast<const float4*>(
                    &Vg[(size_t)(kt0 + key) * D + d4]);
                KVs[key * VP + d4 + 0] = split_tf32(vv.x);
                KVs[key * VP + d4 + 1] = split_tf32(vv.y);
                KVs[key * VP + d4 + 2] = split_tf32(vv.z);
                KVs[key * VP + d4 + 3] = split_tf32(vv.w);
            }
        }
        __syncthreads();

        // ---- O += P V (3x tf32), k-dim = 32 keys ----
#pragma unroll
        for (int ks = 0; ks < 4; ks++) {
            uint32_t ahi[4], alo[4];
#pragma unroll
            for (int r = 0; r < 4; r++) {
                float2 p = Ps[(ks * 8 + tig + (r >> 1) * 4) * PP
                              + (w16 + gid + (r & 1) * 8)];
                ahi[r] = __float_as_uint(p.x);
                alo[r] = __float_as_uint(p.y);
            }
#pragma unroll
            for (int nf = 0; nf < 16; nf++) {
                float2 p0 = KVs[(ks * 8 + tig) * VP + nf * 8 + gid];
                float2 p1 = KVs[(ks * 8 + tig + 4) * VP + nf * 8 + gid];
                uint32_t bhi[2] = {__float_as_uint(p0.x), __float_as_uint(p1.x)};
                uint32_t blo[2] = {__float_as_uint(p0.y), __float_as_uint(p1.y)};
                mma_tf32(o_acc[nf], ahi, bhi);
                mma_tf32(o_acc[nf], ahi, blo);
                mma_tf32(o_acc[nf], alo, bhi);
            }
        }
    }

    // ---- epilogue: O /= l, write [B,T,H*D] ----
    float inv[2] = {1.f / l_i[0], 1.f / l_i[1]};
#pragma unroll
    for (int nf = 0; nf < 16; nf++)
#pragma unroll
        for (int r01 = 0; r01 < 2; r01++) {
            int qrow = m0 + w16 + gid + r01 * 8;
            int dcol = nf * 8 + tig * 2;
            float2 ov;
            ov.x = o_acc[nf][r01 * 2 + 0] * inv[r01];
            ov.y = o_acc[nf][r01 * 2 + 1] * inv[r01];
            *reinterpret_cast<float2*>(
                &o[((size_t)b * T + qrow) * (H * D) + h * D + dcol]) = ov;
        }
}

// ---------------------------------------------------------------------------
// RoPE on [B,NH,T,D], positions t >= LP.
// ---------------------------------------------------------------------------
__global__ void __launch_bounds__(256)
rope_kernel(float* __restrict__ x, const float* __restrict__ cosp,
            const float* __restrict__ sinp, int NH)
{
    int idx = blockIdx.x * 256 + threadIdx.x;
    int d = idx & 63;
    int rest = idx >> 6;
    int t = rest % LSEQ + LP;
    int bh = rest / LSEQ;
    int b = bh / NH, h = bh % NH;

    size_t base  = ((size_t)(b * NH + h) * T + t) * D;
    size_t cbase = ((size_t)b * LSEQ + (t - LP)) * D;

    float x1 = x[base + d], x2 = x[base + d + 64];
    float c1 = cosp[cbase + d],      s1 = sinp[cbase + d];
    float c2 = cosp[cbase + d + 64], s2 = sinp[cbase + d + 64];
    x[base + d]      = x1 * c1 - x2 * s1;
    x[base + d + 64] = x2 * c2 + x1 * s2;
}

// ---------------------------------------------------------------------------
// Launch
// ---------------------------------------------------------------------------
extern "C" void kernel_launch(void* const* d_in, const int* in_sizes, int n_in,
                              void* d_out, int out_size)
{
    (void)in_sizes; (void)n_in; (void)out_size;
    const float* hs   = (const float*)d_in[0];
    const float* cosp = (const float*)d_in[1];
    const float* sinp = (const float*)d_in[2];
    const float* Wq   = (const float*)d_in[3];
    const float* bq   = (const float*)d_in[4];
    const float* Wk   = (const float*)d_in[5];
    const float* bk   = (const float*)d_in[6];
    const float* Wv   = (const float*)d_in[7];
    const float* bv   = (const float*)d_in[8];
    const float* Wo   = (const float*)d_in[9];
    float* out = (float*)d_out;

    float *q, *k, *v, *o;
    cudaGetSymbolAddress((void**)&q, g_q);
    cudaGetSymbolAddress((void**)&k, g_k);
    cudaGetSymbolAddress((void**)&v, g_v);
    cudaGetSymbolAddress((void**)&o, g_o);

    cudaFuncSetAttribute(flash_attn,
                         cudaFuncAttributeMaxDynamicSharedMemorySize,
                         (int)FLASH_SMEM);

    const int M = B * T;  // 4096

    // QKV projections (tensor cores, scatter to [B,heads,T,D])
    proj_mma<<<dim3((H * D) / 128, M / 128), 256>>>(hs, Wq, bq, q, H * D, C, H);
    proj_mma<<<dim3((KV * D) / 128, M / 128), 256>>>(hs, Wk, bk, k, KV * D, C, KV);
    proj_mma<<<dim3((KV * D) / 128, M / 128), 256>>>(hs, Wv, bv, v, KV * D, C, KV);

    // RoPE
    rope_kernel<<<(B * H * LSEQ * 64) / 256, 256>>>(q, cosp, sinp, H);
    rope_kernel<<<(B * KV * LSEQ * 64) / 256, 256>>>(k, cosp, sinp, KV);

    // Fused attention (scores + softmax + PV)
    flash_attn<<<dim3(T / 128, B * H), 256, FLASH_SMEM>>>(q, k, v, o);

    // Output projection
    proj_mma<<<dim3(C / 128, M / 128), 256>>>(o, Wo, nullptr, out, C, H * D, 0);
}

// round 9
// speedup vs baseline: 1.2471x; 1.0005x over previous
#include <cuda_runtime.h>
#include <cuda_bf16.h>
#include <math.h>
#include <stdint.h>

#define B   2
#define T   2048
#define C   2048
#define H   16
#define KV  4
#define D   128
#define LP  64
#define GROUPS (H / KV)
#define LSEQ (T - LP)            // 1984
#define SCALE 0.08838834764831845f   // 1/sqrt(128)

// ---------------- scratch (static device globals: allowed) ----------------
__device__ float g_q[(size_t)B * H * T * D];          // [B,H,T,D]
__device__ float g_k[(size_t)B * KV * T * D];         // [B,KV,T,D]
__device__ float g_v[(size_t)B * KV * T * D];         // [B,KV,T,D]
__device__ float g_o[(size_t)B * T * H * D];          // [B,T,H*D]

// ---------------------------------------------------------------------------
// tf32 helpers
// ---------------------------------------------------------------------------
__device__ __forceinline__ uint32_t f2tf(float x) {
    uint32_t r;
    asm("cvt.rna.tf32.f32 %0, %1;" : "=r"(r) : "f"(x));
    return r;
}

__device__ __forceinline__ float2 split_tf32(float x) {
    uint32_t hi = f2tf(x);
    uint32_t lo = f2tf(x - __uint_as_float(hi));
    float2 p;
    p.x = __uint_as_float(hi);
    p.y = __uint_as_float(lo);
    return p;
}

__device__ __forceinline__ void mma_tf32(float c[4],
                                         const uint32_t a[4],
                                         const uint32_t b[2]) {
    asm volatile(
        "mma.sync.aligned.m16n8k8.row.col.f32.tf32.tf32.f32 "
        "{%0,%1,%2,%3},{%4,%5,%6,%7},{%8,%9},{%0,%1,%2,%3};"
        : "+f"(c[0]), "+f"(c[1]), "+f"(c[2]), "+f"(c[3])
        : "r"(a[0]), "r"(a[1]), "r"(a[2]), "r"(a[3]), "r"(b[0]), "r"(b[1]));
}

// ===========================================================================
// R5 GEMM core (register-side split) — proven, used for all projections.
// ===========================================================================
template<bool TRANSB>
__device__ __forceinline__ void gemm_core(const float* __restrict__ A,
                                          const float* __restrict__ Bm,
                                          int Kdim, int lda, int ldb,
                                          int m0, int n0,
                                          float acc[4][4][4])
{
    __shared__ float As[16][136];
    __shared__ float Bs[16][136];

    const int tid  = threadIdx.x;
    const int lane = tid & 31;
    const int warp = tid >> 5;
    const int gid  = lane >> 2;
    const int tig  = lane & 3;
    const int wm   = (warp >> 2) * 64;
    const int wn   = (warp & 3) * 32;

    const int ar  = tid >> 2;
    const int ac4 = (tid & 3) * 4;
    const int br  = tid >> 4;
    const int bc  = (tid & 15) * 4;

    for (int k0 = 0; k0 < Kdim; k0 += 16) {
#pragma unroll
        for (int half = 0; half < 2; half++) {
            int row = ar + half * 64;
            float4 v = *reinterpret_cast<const float4*>(
                &A[(size_t)(m0 + row) * lda + k0 + ac4]);
            As[ac4 + 0][row] = v.x; As[ac4 + 1][row] = v.y;
            As[ac4 + 2][row] = v.z; As[ac4 + 3][row] = v.w;
        }
        if (TRANSB) {
#pragma unroll
            for (int half = 0; half < 2; half++) {
                int row = ar + half * 64;
                float4 v = *reinterpret_cast<const float4*>(
                    &Bm[(size_t)(n0 + row) * ldb + k0 + ac4]);
                Bs[ac4 + 0][row] = v.x; Bs[ac4 + 1][row] = v.y;
                Bs[ac4 + 2][row] = v.z; Bs[ac4 + 3][row] = v.w;
            }
        } else {
#pragma unroll
            for (int half = 0; half < 2; half++) {
                *reinterpret_cast<float4*>(&Bs[br][bc + half * 64]) =
                    *reinterpret_cast<const float4*>(
                        &Bm[(size_t)(k0 + br) * ldb + n0 + bc + half * 64]);
            }
        }
        __syncthreads();

#pragma unroll
        for (int ks = 0; ks < 2; ks++) {
            uint32_t ahi[4][4], alo[4][4];
#pragma unroll
            for (int mf = 0; mf < 4; mf++)
#pragma unroll
                for (int r = 0; r < 4; r++) {
                    int krow = ks * 8 + tig + (r >> 1) * 4;
                    int mcol = wm + mf * 16 + gid + (r & 1) * 8;
                    float a = As[krow][mcol];
                    uint32_t hi = f2tf(a);
                    ahi[mf][r] = hi;
                    alo[mf][r] = f2tf(a - __uint_as_float(hi));
                }
            uint32_t bhi[4][2], blo[4][2];
#pragma unroll
            for (int nf = 0; nf < 4; nf++)
#pragma unroll
                for (int r = 0; r < 2; r++) {
                    int krow = ks * 8 + tig + r * 4;
                    int ncol = wn + nf * 8 + gid;
                    float b = Bs[krow][ncol];
                    uint32_t hi = f2tf(b);
                    bhi[nf][r] = hi;
                    blo[nf][r] = f2tf(b - __uint_as_float(hi));
                }
#pragma unroll
            for (int mf = 0; mf < 4; mf++)
#pragma unroll
                for (int nf = 0; nf < 4; nf++) {
                    mma_tf32(acc[mf][nf], ahi[mf], bhi[nf]);
                    mma_tf32(acc[mf][nf], ahi[mf], blo[nf]);
                    mma_tf32(acc[mf][nf], alo[mf], bhi[nf]);
                }
        }
        __syncthreads();
    }
}

#define EPI_LOOP(ROW_EXPR, COL_EXPR, ...)                                    \
    {                                                                        \
        const int lane = threadIdx.x & 31;                                   \
        const int warp = threadIdx.x >> 5;                                   \
        const int gid = lane >> 2, tig = lane & 3;                           \
        const int wm = (warp >> 2) * 64, wn = (warp & 3) * 32;               \
        _Pragma("unroll") for (int mf = 0; mf < 4; mf++)                     \
        _Pragma("unroll") for (int nf = 0; nf < 4; nf++)                     \
        _Pragma("unroll") for (int r = 0; r < 4; r++) {                      \
            int row = (ROW_EXPR) + wm + mf * 16 + gid + ((r >> 1) * 8);      \
            int col = (COL_EXPR) + wn + nf * 8 + tig * 2 + (r & 1);          \
            float val = acc[mf][nf][r];                                      \
            __VA_ARGS__                                                      \
        }                                                                    \
    }

__global__ void __launch_bounds__(256)
proj_mma(const float* __restrict__ A, const float* __restrict__ W,
         const float* __restrict__ bias, float* __restrict__ out,
         int N, int Kdim, int NH)
{
    const int m0 = blockIdx.y * 128, n0 = blockIdx.x * 128;
    float acc[4][4][4] = {};
    gemm_core<false>(A, W, Kdim, Kdim, N, m0, n0, acc);

    EPI_LOOP(m0, n0, {
        val += bias ? bias[col] : 0.f;
        if (NH > 0) {
            int b = row / T;
            int t = row % T;
            int h = col >> 7;
            int d = col & 127;
            out[(((size_t)(b * NH + h)) * T + t) * D + d] = val;
        } else {
            out[(size_t)row * N + col] = val;
        }
    })
}

// ===========================================================================
// Fused flash attention: scores + online softmax + PV in one kernel.
// Block: 256 threads (8 warps), Q tile = 128 rows (warp w owns rows w*16..+16).
// KV processed in tiles of 32 keys. All smem operands stored as split
// tf32 (hi,lo) float2 with pitch ≡ 4 mod 16 f2 → conflict-free frag reads.
// ===========================================================================
#define KTILE 32
#define NTILES (T / KTILE)   // 64
#define QP 132               // f2 pitch, [128 d][m]
#define KP 36                // f2 pitch, [128 d][key^swz]
#define VP 132               // f2 pitch, [32 key][d]
#define PP 132               // f2 pitch, [32 key][m]
#define FLASH_SMEM ((128 * QP + 128 * KP + KTILE * PP) * sizeof(float2))

__global__ void __launch_bounds__(256, 1)
flash_attn(const float* __restrict__ q, const float* __restrict__ k,
           const float* __restrict__ v, float* __restrict__ o)
{
    extern __shared__ float2 sm[];
    float2* Qs  = sm;                       // [d][m]
    float2* KVs = sm + 128 * QP;            // K: [d][key^swz]  /  V: [key][d]
    float2* Ps  = KVs + 128 * KP;           // [key][m]

    const int tid  = threadIdx.x;
    const int lane = tid & 31, warp = tid >> 5;
    const int gid  = lane >> 2, tig = lane & 3;
    const int w16  = warp * 16;

    const int m0 = blockIdx.x * 128;
    const int bh = blockIdx.y;
    const int b  = bh / H, h = bh % H;

    const float* Qg = q + ((size_t)(b * H + h) * T + m0) * D;
    const float* Kg = k + (size_t)(b * KV + h / GROUPS) * T * D;
    const float* Vg = v + (size_t)(b * KV + h / GROUPS) * T * D;

    // ---- load Q tile once, split, store transposed [d][m] ----
    {
        int row = tid >> 1;
#pragma unroll
        for (int j = 0; j < 16; j++) {
            int d4 = (tid & 1) * 4 + j * 8;
            float4 qv = *reinterpret_cast<const float4*>(&Qg[(size_t)row * D + d4]);
            Qs[(d4 + 0) * QP + row] = split_tf32(qv.x);
            Qs[(d4 + 1) * QP + row] = split_tf32(qv.y);
            Qs[(d4 + 2) * QP + row] = split_tf32(qv.z);
            Qs[(d4 + 3) * QP + row] = split_tf32(qv.w);
        }
    }

    float o_acc[16][4];
#pragma unroll
    for (int nf = 0; nf < 16; nf++)
#pragma unroll
        for (int r = 0; r < 4; r++) o_acc[nf][r] = 0.f;
    float m_i[2] = {-1e30f, -1e30f};
    float l_i[2] = {0.f, 0.f};

    for (int tile = 0; tile < NTILES; tile++) {
        const int kt0 = tile * KTILE;
        __syncthreads();   // prev PV reads of KVs done

        // ---- load K tile -> KVs[d][key ^ ((d>>2)&7)] ----
        {
            int key = tid >> 3;
            int swz = tid & 7;               // = ((d4+i)>>2)&7 for all i<4
            int kcol = key ^ swz;
#pragma unroll
            for (int j = 0; j < 4; j++) {
                int d4 = (tid & 7) * 4 + j * 32;
                float4 kv = *reinterpret_cast<const float4*>(
                    &Kg[(size_t)(kt0 + key) * D + d4]);
                KVs[(d4 + 0) * KP + kcol] = split_tf32(kv.x);
                KVs[(d4 + 1) * KP + kcol] = split_tf32(kv.y);
                KVs[(d4 + 2) * KP + kcol] = split_tf32(kv.z);
                KVs[(d4 + 3) * KP + kcol] = split_tf32(kv.w);
            }
        }
        __syncthreads();

        // ---- S = Q K^T (3x tf32), warp tile 16 rows x 32 keys ----
        float s[4][4];
#pragma unroll
        for (int nf = 0; nf < 4; nf++)
#pragma unroll
            for (int r = 0; r < 4; r++) s[nf][r] = 0.f;

#pragma unroll
        for (int ks = 0; ks < 16; ks++) {
            uint32_t ahi[4], alo[4];
#pragma unroll
            for (int r = 0; r < 4; r++) {
                float2 p = Qs[(ks * 8 + tig + (r >> 1) * 4) * QP
                              + (w16 + gid + (r & 1) * 8)];
                ahi[r] = __float_as_uint(p.x);
                alo[r] = __float_as_uint(p.y);
            }
            const int swz0 = (2 * ks) & 7;
            const int swz1 = (2 * ks + 1) & 7;
#pragma unroll
            for (int nf = 0; nf < 4; nf++) {
                float2 p0 = KVs[(ks * 8 + tig) * KP + ((nf * 8 + gid) ^ swz0)];
                float2 p1 = KVs[(ks * 8 + tig + 4) * KP + ((nf * 8 + gid) ^ swz1)];
                uint32_t bhi[2] = {__float_as_uint(p0.x), __float_as_uint(p1.x)};
                uint32_t blo[2] = {__float_as_uint(p0.y), __float_as_uint(p1.y)};
                mma_tf32(s[nf], ahi, bhi);
                mma_tf32(s[nf], ahi, blo);
                mma_tf32(s[nf], alo, bhi);
            }
        }

        // ---- bias + scale + online softmax (rows warp-local) ----
        float mx[2] = {-1e30f, -1e30f};
#pragma unroll
        for (int nf = 0; nf < 4; nf++)
#pragma unroll
            for (int r = 0; r < 4; r++) {
                int j = kt0 + nf * 8 + tig * 2 + (r & 1);
                int qrow = m0 + w16 + gid + (r >> 1) * 8;
                float bias = ((j < LP) || (qrow >= LP && j <= qrow)) ? 1.0f : 0.0f;
                float val = s[nf][r] * SCALE + bias;
                s[nf][r] = val;
                mx[r >> 1] = fmaxf(mx[r >> 1], val);
            }
        float sf[2];
#pragma unroll
        for (int r01 = 0; r01 < 2; r01++) {
            float m = mx[r01];
            m = fmaxf(m, __shfl_xor_sync(0xffffffffu, m, 1));
            m = fmaxf(m, __shfl_xor_sync(0xffffffffu, m, 2));
            float m_new = fmaxf(m_i[r01], m);
            sf[r01] = __expf(m_i[r01] - m_new);
            m_i[r01] = m_new;
        }
        float sum[2] = {0.f, 0.f};
#pragma unroll
        for (int nf = 0; nf < 4; nf++)
#pragma unroll
            for (int r = 0; r < 4; r++) {
                float p = __expf(s[nf][r] - m_i[r >> 1]);
                sum[r >> 1] += p;
                Ps[(nf * 8 + tig * 2 + (r & 1)) * PP
                   + (w16 + gid + (r >> 1) * 8)] = split_tf32(p);
            }
#pragma unroll
        for (int r01 = 0; r01 < 2; r01++) {
            float ssum = sum[r01];
            ssum += __shfl_xor_sync(0xffffffffu, ssum, 1);
            ssum += __shfl_xor_sync(0xffffffffu, ssum, 2);
            l_i[r01] = l_i[r01] * sf[r01] + ssum;
        }
#pragma unroll
        for (int nf = 0; nf < 16; nf++)
#pragma unroll
            for (int r = 0; r < 4; r++) o_acc[nf][r] *= sf[r >> 1];

        __syncthreads();   // all warps done reading K

        // ---- load V tile -> KVs[key][d] ----
        {
            int key = tid >> 3;
#pragma unroll
            for (int j = 0; j < 4; j++) {
                int d4 = (tid & 7) * 4 + j * 32;
                float4 vv = *reinterpret_cast<const float4*>(
                    &Vg[(size_t)(kt0 + key) * D + d4]);
                KVs[key * VP + d4 + 0] = split_tf32(vv.x);
                KVs[key * VP + d4 + 1] = split_tf32(vv.y);
                KVs[key * VP + d4 + 2] = split_tf32(vv.z);
                KVs[key * VP + d4 + 3] = split_tf32(vv.w);
            }
        }
        __syncthreads();

        // ---- O += P V (3x tf32), k-dim = 32 keys ----
#pragma unroll
        for (int ks = 0; ks < 4; ks++) {
            uint32_t ahi[4], alo[4];
#pragma unroll
            for (int r = 0; r < 4; r++) {
                float2 p = Ps[(ks * 8 + tig + (r >> 1) * 4) * PP
                              + (w16 + gid + (r & 1) * 8)];
                ahi[r] = __float_as_uint(p.x);
                alo[r] = __float_as_uint(p.y);
            }
#pragma unroll
            for (int nf = 0; nf < 16; nf++) {
                float2 p0 = KVs[(ks * 8 + tig) * VP + nf * 8 + gid];
                float2 p1 = KVs[(ks * 8 + tig + 4) * VP + nf * 8 + gid];
                uint32_t bhi[2] = {__float_as_uint(p0.x), __float_as_uint(p1.x)};
                uint32_t blo[2] = {__float_as_uint(p0.y), __float_as_uint(p1.y)};
                mma_tf32(o_acc[nf], ahi, bhi);
                mma_tf32(o_acc[nf], ahi, blo);
                mma_tf32(o_acc[nf], alo, bhi);
            }
        }
    }

    // ---- epilogue: O /= l, write [B,T,H*D] ----
    float inv[2] = {1.f / l_i[0], 1.f / l_i[1]};
#pragma unroll
    for (int nf = 0; nf < 16; nf++)
#pragma unroll
        for (int r01 = 0; r01 < 2; r01++) {
            int qrow = m0 + w16 + gid + r01 * 8;
            int dcol = nf * 8 + tig * 2;
            float2 ov;
            ov.x = o_acc[nf][r01 * 2 + 0] * inv[r01];
            ov.y = o_acc[nf][r01 * 2 + 1] * inv[r01];
            *reinterpret_cast<float2*>(
                &o[((size_t)b * T + qrow) * (H * D) + h * D + dcol]) = ov;
        }
}

// ---------------------------------------------------------------------------
// RoPE on [B,NH,T,D], positions t >= LP.
// ---------------------------------------------------------------------------
__global__ void __launch_bounds__(256)
rope_kernel(float* __restrict__ x, const float* __restrict__ cosp,
            const float* __restrict__ sinp, int NH)
{
    int idx = blockIdx.x * 256 + threadIdx.x;
    int d = idx & 63;
    int rest = idx >> 6;
    int t = rest % LSEQ + LP;
    int bh = rest / LSEQ;
    int b = bh / NH, h = bh % NH;

    size_t base  = ((size_t)(b * NH + h) * T + t) * D;
    size_t cbase = ((size_t)b * LSEQ + (t - LP)) * D;

    float x1 = x[base + d], x2 = x[base + d + 64];
    float c1 = cosp[cbase + d],      s1 = sinp[cbase + d];
    float c2 = cosp[cbase + d + 64], s2 = sinp[cbase + d + 64];
    x[base + d]      = x1 * c1 - x2 * s1;
    x[base + d + 64] = x2 * c2 + x1 * s2;
}

// ---------------------------------------------------------------------------
// Launch
// ---------------------------------------------------------------------------
extern "C" void kernel_launch(void* const* d_in, const int* in_sizes, int n_in,
                              void* d_out, int out_size)
{
    (void)in_sizes; (void)n_in; (void)out_size;
    const float* hs   = (const float*)d_in[0];
    const float* cosp = (const float*)d_in[1];
    const float* sinp = (const float*)d_in[2];
    const float* Wq   = (const float*)d_in[3];
    const float* bq   = (const float*)d_in[4];
    const float* Wk   = (const float*)d_in[5];
    const float* bk   = (const float*)d_in[6];
    const float* Wv   = (const float*)d_in[7];
    const float* bv   = (const float*)d_in[8];
    const float* Wo   = (const float*)d_in[9];
    float* out = (float*)d_out;

    float *q, *k, *v, *o;
    cudaGetSymbolAddress((void**)&q, g_q);
    cudaGetSymbolAddress((void**)&k, g_k);
    cudaGetSymbolAddress((void**)&v, g_v);
    cudaGetSymbolAddress((void**)&o, g_o);

    cudaFuncSetAttribute(flash_attn,
                         cudaFuncAttributeMaxDynamicSharedMemorySize,
                         (int)FLASH_SMEM);

    const int M = B * T;  // 4096

    // QKV projections (tensor cores, scatter to [B,heads,T,D])
    proj_mma<<<dim3((H * D) / 128, M / 128), 256>>>(hs, Wq, bq, q, H * D, C, H);
    proj_mma<<<dim3((KV * D) / 128, M / 128), 256>>>(hs, Wk, bk, k, KV * D, C, KV);
    proj_mma<<<dim3((KV * D) / 128, M / 128), 256>>>(hs, Wv, bv, v, KV * D, C, KV);

    // RoPE
    rope_kernel<<<(B * H * LSEQ * 64) / 256, 256>>>(q, cosp, sinp, H);
    rope_kernel<<<(B * KV * LSEQ * 64) / 256, 256>>>(k, cosp, sinp, KV);

    // Fused attention (scores + softmax + PV)
    flash_attn<<<dim3(T / 128, B * H), 256, FLASH_SMEM>>>(q, k, v, o);

    // Output projection
    proj_mma<<<dim3(C / 128, M / 128), 256>>>(o, Wo, nullptr, out, C, H * D, 0);
}

// round 10
// speedup vs baseline: 2.3737x; 1.9034x over previous
#include <cuda_runtime.h>
#include <cuda_bf16.h>
#include <math.h>
#include <stdint.h>

#define B   2
#define T   2048
#define C   2048
#define H   16
#define KV  4
#define D   128
#define LP  64
#define GROUPS (H / KV)
#define LSEQ (T - LP)            // 1984
#define SCALE 0.08838834764831845f   // 1/sqrt(128)

// ---------------- scratch (static device globals: allowed) ----------------
__device__ float g_q[(size_t)B * H * T * D];          // [B,H,T,D]
__device__ float g_k[(size_t)B * KV * T * D];         // [B,KV,T,D]
__device__ float g_v[(size_t)B * KV * T * D];         // [B,KV,T,D]
__device__ float g_o[(size_t)B * T * H * D];          // [B,T,H*D]

// ---------------------------------------------------------------------------
// bf16x3 helpers: split fp32 pair -> (bf16x2 hi, bf16x2 lo)
// cvt.rn.bf16x2.f32 d,a,b : a->high half, b->low half. We want x0 in low.
// ---------------------------------------------------------------------------
__device__ __forceinline__ uint2 split2(float x0, float x1) {
    uint32_t hi;
    asm("cvt.rn.bf16x2.f32 %0, %1, %2;" : "=r"(hi) : "f"(x1), "f"(x0));
    float h0 = __uint_as_float(hi << 16);
    float h1 = __uint_as_float(hi & 0xffff0000u);
    uint32_t lo;
    float l0 = x0 - h0, l1 = x1 - h1;
    asm("cvt.rn.bf16x2.f32 %0, %1, %2;" : "=r"(lo) : "f"(l1), "f"(l0));
    uint2 r; r.x = hi; r.y = lo; return r;
}

__device__ __forceinline__ void mma_bf16(float c[4],
                                         const uint32_t a[4],
                                         const uint32_t b[2]) {
    asm volatile(
        "mma.sync.aligned.m16n8k16.row.col.f32.bf16.bf16.f32 "
        "{%0,%1,%2,%3},{%4,%5,%6,%7},{%8,%9},{%0,%1,%2,%3};"
        : "+f"(c[0]), "+f"(c[1]), "+f"(c[2]), "+f"(c[3])
        : "r"(a[0]), "r"(a[1]), "r"(a[2]), "r"(a[3]), "r"(b[0]), "r"(b[1]));
}

// ===========================================================================
// Projection GEMM (bf16x3): out = A(MxK) @ W(KxN) + bias
// 128x128 tile, k-step 16 (one m16n8k16 per fragment pair), 8 warps 64x32.
// A smem: [m 128][kp 8] pitch 8  -> frag banks gid*8+tig (conflict-free)
// B smem: [kp 8][n 128] pitch 136 -> frag banks tig*8+gid (conflict-free)
// ===========================================================================
__global__ void __launch_bounds__(256)
proj_mma(const float* __restrict__ A, const float* __restrict__ W,
         const float* __restrict__ bias, float* __restrict__ out,
         int N, int Kdim, int NH)
{
    __shared__ uint32_t Ah[128 * 8], Al[128 * 8];
    __shared__ uint32_t Bh[8 * 136], Bl[8 * 136];

    const int tid  = threadIdx.x;
    const int lane = tid & 31;
    const int warp = tid >> 5;
    const int gid  = lane >> 2;
    const int tig  = lane & 3;
    const int wm   = (warp >> 2) * 64;
    const int wn   = (warp & 3) * 32;
    const int m0   = blockIdx.y * 128, n0 = blockIdx.x * 128;

    const int ar  = tid >> 2;           // 0..63 (+64)
    const int ac4 = (tid & 3) * 4;      // k offset
    const int kp0 = (tid & 3) * 2;      // k-pair offset
    const int bkp = tid >> 5;           // 0..7 k-pair row for B
    const int bn  = (tid & 31) * 4;     // n offset for B

    float acc[4][4][4] = {};

    for (int k0 = 0; k0 < Kdim; k0 += 16) {
        // ---- A tile ----
#pragma unroll
        for (int half = 0; half < 2; half++) {
            int row = ar + half * 64;
            float4 v = *reinterpret_cast<const float4*>(
                &A[(size_t)(m0 + row) * Kdim + k0 + ac4]);
            uint2 p0 = split2(v.x, v.y);
            uint2 p1 = split2(v.z, v.w);
            *reinterpret_cast<uint2*>(&Ah[row * 8 + kp0]) = make_uint2(p0.x, p1.x);
            *reinterpret_cast<uint2*>(&Al[row * 8 + kp0]) = make_uint2(p0.y, p1.y);
        }
        // ---- B tile: rows k0+2*bkp, k0+2*bkp+1 ----
        {
            const float* W0 = &W[(size_t)(k0 + 2 * bkp) * N + n0 + bn];
            float4 v0 = *reinterpret_cast<const float4*>(W0);
            float4 v1 = *reinterpret_cast<const float4*>(W0 + N);
            uint2 q0 = split2(v0.x, v1.x);
            uint2 q1 = split2(v0.y, v1.y);
            uint2 q2 = split2(v0.z, v1.z);
            uint2 q3 = split2(v0.w, v1.w);
            *reinterpret_cast<uint4*>(&Bh[bkp * 136 + bn]) =
                make_uint4(q0.x, q1.x, q2.x, q3.x);
            *reinterpret_cast<uint4*>(&Bl[bkp * 136 + bn]) =
                make_uint4(q0.y, q1.y, q2.y, q3.y);
        }
        __syncthreads();

        uint32_t ahi[4][4], alo[4][4];
#pragma unroll
        for (int mf = 0; mf < 4; mf++) {
            int r0 = (wm + mf * 16 + gid) * 8;
            ahi[mf][0] = Ah[r0 + tig];
            ahi[mf][1] = Ah[r0 + 64 + tig];
            ahi[mf][2] = Ah[r0 + tig + 4];
            ahi[mf][3] = Ah[r0 + 64 + tig + 4];
            alo[mf][0] = Al[r0 + tig];
            alo[mf][1] = Al[r0 + 64 + tig];
            alo[mf][2] = Al[r0 + tig + 4];
            alo[mf][3] = Al[r0 + 64 + tig + 4];
        }
#pragma unroll
        for (int nf = 0; nf < 4; nf++) {
            int cb = wn + nf * 8 + gid;
            uint32_t bhi[2] = {Bh[tig * 136 + cb], Bh[(tig + 4) * 136 + cb]};
            uint32_t blo[2] = {Bl[tig * 136 + cb], Bl[(tig + 4) * 136 + cb]};
#pragma unroll
            for (int mf = 0; mf < 4; mf++) {
                mma_bf16(acc[mf][nf], ahi[mf], bhi);
                mma_bf16(acc[mf][nf], ahi[mf], blo);
                mma_bf16(acc[mf][nf], alo[mf], bhi);
            }
        }
        __syncthreads();
    }

    // epilogue
#pragma unroll
    for (int mf = 0; mf < 4; mf++)
#pragma unroll
        for (int nf = 0; nf < 4; nf++)
#pragma unroll
            for (int r = 0; r < 4; r++) {
                int row = m0 + wm + mf * 16 + gid + (r >> 1) * 8;
                int col = n0 + wn + nf * 8 + tig * 2 + (r & 1);
                float val = acc[mf][nf][r] + (bias ? bias[col] : 0.f);
                if (NH > 0) {
                    int b = row / T;
                    int t = row % T;
                    int h = col >> 7;
                    int d = col & 127;
                    out[(((size_t)(b * NH + h)) * T + t) * D + d] = val;
                } else {
                    out[(size_t)row * N + col] = val;
                }
            }
}

// ===========================================================================
// Fused flash attention (bf16x3): scores + online softmax + PV.
// 256 threads / 8 warps; Q tile 128 rows (warp w owns rows w*16..+15);
// KV tiles of 32 keys.
// Q,K smem [row][dpair] pitch 68; P [m][jpair] pitch 20; V [jpair][d] pitch 136.
// All fragment LDS patterns conflict-free (verified mod-32).
// ===========================================================================
#define KTILE 32
#define NTILES (T / KTILE)   // 64
#define QW (128 * 68)
#define KW (32 * 68)
#define PW (128 * 20)
#define VW (16 * 136)
#define FLASH_SMEM ((2 * (QW + KW + PW + VW)) * sizeof(uint32_t))

__global__ void __launch_bounds__(256, 1)
flash_attn(const float* __restrict__ q, const float* __restrict__ k,
           const float* __restrict__ v, float* __restrict__ o)
{
    extern __shared__ uint32_t sm[];
    uint32_t* Qh = sm;
    uint32_t* Ql = Qh + QW;
    uint32_t* Kh = Ql + QW;
    uint32_t* Kl = Kh + KW;
    uint32_t* Ph = Kl + KW;
    uint32_t* Pl = Ph + PW;
    uint32_t* Vh = Pl + PW;
    uint32_t* Vl = Vh + VW;

    const int tid  = threadIdx.x;
    const int lane = tid & 31, warp = tid >> 5;
    const int gid  = lane >> 2, tig = lane & 3;
    const int w16  = warp * 16;

    const int m0 = blockIdx.x * 128;
    const int bh = blockIdx.y;
    const int b  = bh / H, h = bh % H;

    const float* Qg = q + ((size_t)(b * H + h) * T + m0) * D;
    const float* Kg = k + (size_t)(b * KV + h / GROUPS) * T * D;
    const float* Vg = v + (size_t)(b * KV + h / GROUPS) * T * D;

    // ---- load Q tile once, split -> [row][dp] ----
    {
        int row = tid >> 1;
#pragma unroll
        for (int j = 0; j < 16; j++) {
            int d4 = (tid & 1) * 4 + j * 8;
            float4 qv = *reinterpret_cast<const float4*>(&Qg[(size_t)row * D + d4]);
            uint2 p0 = split2(qv.x, qv.y);
            uint2 p1 = split2(qv.z, qv.w);
            *reinterpret_cast<uint2*>(&Qh[row * 68 + d4 / 2]) = make_uint2(p0.x, p1.x);
            *reinterpret_cast<uint2*>(&Ql[row * 68 + d4 / 2]) = make_uint2(p0.y, p1.y);
        }
    }

    float o_acc[16][4];
#pragma unroll
    for (int nf = 0; nf < 16; nf++)
#pragma unroll
        for (int r = 0; r < 4; r++) o_acc[nf][r] = 0.f;
    float m_i[2] = {-1e30f, -1e30f};
    float l_i[2] = {0.f, 0.f};

    for (int tile = 0; tile < NTILES; tile++) {
        const int kt0 = tile * KTILE;
        __syncthreads();   // prev tile's K/V/P reads complete

        // ---- K tile -> [key][dp] ----
        {
            int key = tid >> 3;
#pragma unroll
            for (int j = 0; j < 4; j++) {
                int d4 = (tid & 7) * 4 + j * 32;
                float4 kv = *reinterpret_cast<const float4*>(
                    &Kg[(size_t)(kt0 + key) * D + d4]);
                uint2 p0 = split2(kv.x, kv.y);
                uint2 p1 = split2(kv.z, kv.w);
                *reinterpret_cast<uint2*>(&Kh[key * 68 + d4 / 2]) = make_uint2(p0.x, p1.x);
                *reinterpret_cast<uint2*>(&Kl[key * 68 + d4 / 2]) = make_uint2(p0.y, p1.y);
            }
        }
        // ---- V tile -> [jp][d] (pairs along keys) ----
        {
            int jp = tid >> 4;
#pragma unroll
            for (int j = 0; j < 2; j++) {
                int d = (tid & 15) * 4 + j * 64;
                float4 v0 = *reinterpret_cast<const float4*>(
                    &Vg[(size_t)(kt0 + 2 * jp) * D + d]);
                float4 v1 = *reinterpret_cast<const float4*>(
                    &Vg[(size_t)(kt0 + 2 * jp + 1) * D + d]);
                uint2 q0 = split2(v0.x, v1.x);
                uint2 q1 = split2(v0.y, v1.y);
                uint2 q2 = split2(v0.z, v1.z);
                uint2 q3 = split2(v0.w, v1.w);
                *reinterpret_cast<uint4*>(&Vh[jp * 136 + d]) =
                    make_uint4(q0.x, q1.x, q2.x, q3.x);
                *reinterpret_cast<uint4*>(&Vl[jp * 136 + d]) =
                    make_uint4(q0.y, q1.y, q2.y, q3.y);
            }
        }
        __syncthreads();

        // ---- S = Q K^T : 8 k16 steps over d=128 ----
        float s[4][4];
#pragma unroll
        for (int nf = 0; nf < 4; nf++)
#pragma unroll
            for (int r = 0; r < 4; r++) s[nf][r] = 0.f;

#pragma unroll
        for (int ks = 0; ks < 8; ks++) {
            uint32_t ahi[4], alo[4];
            int qb = (w16 + gid) * 68 + ks * 8 + tig;
            ahi[0] = Qh[qb];            ahi[1] = Qh[qb + 8 * 68];
            ahi[2] = Qh[qb + 4];        ahi[3] = Qh[qb + 8 * 68 + 4];
            alo[0] = Ql[qb];            alo[1] = Ql[qb + 8 * 68];
            alo[2] = Ql[qb + 4];        alo[3] = Ql[qb + 8 * 68 + 4];
#pragma unroll
            for (int nf = 0; nf < 4; nf++) {
                int kb = (nf * 8 + gid) * 68 + ks * 8 + tig;
                uint32_t bhi[2] = {Kh[kb], Kh[kb + 4]};
                uint32_t blo[2] = {Kl[kb], Kl[kb + 4]};
                mma_bf16(s[nf], ahi, bhi);
                mma_bf16(s[nf], ahi, blo);
                mma_bf16(s[nf], alo, bhi);
            }
        }

        // ---- bias + scale + online softmax ----
        float mx[2] = {-1e30f, -1e30f};
#pragma unroll
        for (int nf = 0; nf < 4; nf++)
#pragma unroll
            for (int r = 0; r < 4; r++) {
                int j = kt0 + nf * 8 + tig * 2 + (r & 1);
                int qrow = m0 + w16 + gid + (r >> 1) * 8;
                float bias = ((j < LP) || (qrow >= LP && j <= qrow)) ? 1.0f : 0.0f;
                float val = s[nf][r] * SCALE + bias;
                s[nf][r] = val;
                mx[r >> 1] = fmaxf(mx[r >> 1], val);
            }
        float sf[2];
#pragma unroll
        for (int r01 = 0; r01 < 2; r01++) {
            float m = mx[r01];
            m = fmaxf(m, __shfl_xor_sync(0xffffffffu, m, 1));
            m = fmaxf(m, __shfl_xor_sync(0xffffffffu, m, 2));
            float m_new = fmaxf(m_i[r01], m);
            sf[r01] = __expf(m_i[r01] - m_new);
            m_i[r01] = m_new;
        }
        float sum[2] = {0.f, 0.f};
#pragma unroll
        for (int nf = 0; nf < 4; nf++)
#pragma unroll
            for (int r01 = 0; r01 < 2; r01++) {
                float p0 = __expf(s[nf][r01 * 2 + 0] - m_i[r01]);
                float p1 = __expf(s[nf][r01 * 2 + 1] - m_i[r01]);
                sum[r01] += p0 + p1;
                uint2 pp = split2(p0, p1);
                int idx = (w16 + gid + r01 * 8) * 20 + nf * 4 + tig;
                Ph[idx] = pp.x;
                Pl[idx] = pp.y;
            }
#pragma unroll
        for (int r01 = 0; r01 < 2; r01++) {
            float ssum = sum[r01];
            ssum += __shfl_xor_sync(0xffffffffu, ssum, 1);
            ssum += __shfl_xor_sync(0xffffffffu, ssum, 2);
            l_i[r01] = l_i[r01] * sf[r01] + ssum;
        }
#pragma unroll
        for (int nf = 0; nf < 16; nf++)
#pragma unroll
            for (int r = 0; r < 4; r++) o_acc[nf][r] *= sf[r >> 1];

        __syncwarp();   // P rows are warp-private: warp-level sync suffices

        // ---- O += P V : 2 k16 steps over 32 keys ----
#pragma unroll
        for (int ksB = 0; ksB < 2; ksB++) {
            uint32_t ahi[4], alo[4];
            int pb = (w16 + gid) * 20 + ksB * 8 + tig;
            ahi[0] = Ph[pb];            ahi[1] = Ph[pb + 8 * 20];
            ahi[2] = Ph[pb + 4];        ahi[3] = Ph[pb + 8 * 20 + 4];
            alo[0] = Pl[pb];            alo[1] = Pl[pb + 8 * 20];
            alo[2] = Pl[pb + 4];        alo[3] = Pl[pb + 8 * 20 + 4];
#pragma unroll
            for (int nf = 0; nf < 16; nf++) {
                int vb = (ksB * 8 + tig) * 136 + nf * 8 + gid;
                uint32_t bhi[2] = {Vh[vb], Vh[vb + 4 * 136]};
                uint32_t blo[2] = {Vl[vb], Vl[vb + 4 * 136]};
                mma_bf16(o_acc[nf], ahi, bhi);
                mma_bf16(o_acc[nf], ahi, blo);
                mma_bf16(o_acc[nf], alo, bhi);
            }
        }
    }

    // ---- epilogue: O /= l, write [B,T,H*D] ----
    float inv[2] = {1.f / l_i[0], 1.f / l_i[1]};
#pragma unroll
    for (int nf = 0; nf < 16; nf++)
#pragma unroll
        for (int r01 = 0; r01 < 2; r01++) {
            int qrow = m0 + w16 + gid + r01 * 8;
            int dcol = nf * 8 + tig * 2;
            float2 ov;
            ov.x = o_acc[nf][r01 * 2 + 0] * inv[r01];
            ov.y = o_acc[nf][r01 * 2 + 1] * inv[r01];
            *reinterpret_cast<float2*>(
                &o[((size_t)b * T + qrow) * (H * D) + h * D + dcol]) = ov;
        }
}

// ---------------------------------------------------------------------------
// RoPE on [B,NH,T,D], positions t >= LP.
// ---------------------------------------------------------------------------
__global__ void __launch_bounds__(256)
rope_kernel(float* __restrict__ x, const float* __restrict__ cosp,
            const float* __restrict__ sinp, int NH)
{
    int idx = blockIdx.x * 256 + threadIdx.x;
    int d = idx & 63;
    int rest = idx >> 6;
    int t = rest % LSEQ + LP;
    int bh = rest / LSEQ;
    int b = bh / NH, h = bh % NH;

    size_t base  = ((size_t)(b * NH + h) * T + t) * D;
    size_t cbase = ((size_t)b * LSEQ + (t - LP)) * D;

    float x1 = x[base + d], x2 = x[base + d + 64];
    float c1 = cosp[cbase + d],      s1 = sinp[cbase + d];
    float c2 = cosp[cbase + d + 64], s2 = sinp[cbase + d + 64];
    x[base + d]      = x1 * c1 - x2 * s1;
    x[base + d + 64] = x2 * c2 + x1 * s2;
}

// ---------------------------------------------------------------------------
// Launch
// ---------------------------------------------------------------------------
extern "C" void kernel_launch(void* const* d_in, const int* in_sizes, int n_in,
                              void* d_out, int out_size)
{
    (void)in_sizes; (void)n_in; (void)out_size;
    const float* hs   = (const float*)d_in[0];
    const float* cosp = (const float*)d_in[1];
    const float* sinp = (const float*)d_in[2];
    const float* Wq   = (const float*)d_in[3];
    const float* bq   = (const float*)d_in[4];
    const float* Wk   = (const float*)d_in[5];
    const float* bk   = (const float*)d_in[6];
    const float* Wv   = (const float*)d_in[7];
    const float* bv   = (const float*)d_in[8];
    const float* Wo   = (const float*)d_in[9];
    float* out = (float*)d_out;

    float *q, *k, *v, *o;
    cudaGetSymbolAddress((void**)&q, g_q);
    cudaGetSymbolAddress((void**)&k, g_k);
    cudaGetSymbolAddress((void**)&v, g_v);
    cudaGetSymbolAddress((void**)&o, g_o);

    cudaFuncSetAttribute(flash_attn,
                         cudaFuncAttributeMaxDynamicSharedMemorySize,
                         (int)FLASH_SMEM);

    const int M = B * T;  // 4096

    // QKV projections (bf16x3 tensor cores, scatter to [B,heads,T,D])
    proj_mma<<<dim3((H * D) / 128, M / 128), 256>>>(hs, Wq, bq, q, H * D, C, H);
    proj_mma<<<dim3((KV * D) / 128, M / 128), 256>>>(hs, Wk, bk, k, KV * D, C, KV);
    proj_mma<<<dim3((KV * D) / 128, M / 128), 256>>>(hs, Wv, bv, v, KV * D, C, KV);

    // RoPE
    rope_kernel<<<(B * H * LSEQ * 64) / 256, 256>>>(q, cosp, sinp, H);
    rope_kernel<<<(B * KV * LSEQ * 64) / 256, 256>>>(k, cosp, sinp, KV);

    // Fused attention (scores + softmax + PV)
    flash_attn<<<dim3(T / 128, B * H), 256, FLASH_SMEM>>>(q, k, v, o);

    // Output projection
    proj_mma<<<dim3(C / 128, M / 128), 256>>>(o, Wo, nullptr, out, C, H * D, 0);
}